// round 1
// baseline (speedup 1.0000x reference)
#include <cuda_runtime.h>

// Fixed problem structure (from reference setup_inputs):
//   4 nodes/graph (nodes 0..2 = jet, node 3 = muon)
//   12 directed edges/graph in order (i,j) for i in 0..3, j!=i
//   edge (i,j) index within graph = 3*i + (j - (j>i))
// H = 16, MH = 64.

#define NTHREADS 256

// ---- shared memory layout (floats) ----
#define JE_W1 0      // 80
#define JE_B1 80     // 16
#define JE_W2 96     // 256
#define JE_B2 352    // 16
#define MU_W1 368    // 80
#define MU_B1 448    // 16
#define MU_W2 464    // 256
#define MU_B2 720    // 16
#define L1_W  736    // 64
#define L1_B  800    // 16
#define M1_W1 816    // 1024
#define M1_B1 1840   // 64
#define M1_W2 1904   // 1024
#define M1_B2 2928   // 16
#define L2_W  2944   // 64
#define L2_B  3008   // 16
#define M2_W1 3024   // 1024
#define M2_B1 4048   // 64
#define M2_W2 4112   // 1024
#define M2_B2 5136   // 16
#define FC_W1 5152   // 2048
#define FC_B1 7200   // 64
#define FC_W2 7264   // 64
#define SMEM_FLOATS 7328

struct Params {
    const float* x;
    const float* ea;
    const float* w[24];   // je_w1..fc_b2 in metadata order
    float* out;
    int G;
};

__device__ __forceinline__ float4 ld4s(const float* p) {
    return *reinterpret_cast<const float4*>(p);
}

__device__ __forceinline__ void addv4(float* acc, float s, float4 w) {
    acc[0] = fmaf(s, w.x, acc[0]);
    acc[1] = fmaf(s, w.y, acc[1]);
    acc[2] = fmaf(s, w.z, acc[2]);
    acc[3] = fmaf(s, w.w, acc[3]);
}

// one GINE layer + LN + relu, fully in registers; h updated in place
__device__ __forceinline__ void gine_ln_relu(
    float (&h)[16], int lane, int node, int graph,
    const float* __restrict__ ea,
    const float* lw, const float* lb,
    const float* w1, const float* b1,
    const float* w2, const float* b2)
{
    float agg[16];
#pragma unroll
    for (int d = 0; d < 16; d++) agg[d] = 0.f;

    const float* eb = ea + (long long)graph * 48;

#pragma unroll
    for (int m = 1; m < 4; m++) {
        int src = (node + m) & 3;
        int eidx = src * 3 + node - (node > src ? 1 : 0);
        float4 e4 = __ldg(reinterpret_cast<const float4*>(eb + eidx * 4));
        float ev[4] = {e4.x, e4.y, e4.z, e4.w};

        float msg[16];
#pragma unroll
        for (int v = 0; v < 4; v++) {
            float4 b = ld4s(lb + 4 * v);
            msg[4 * v + 0] = b.x; msg[4 * v + 1] = b.y;
            msg[4 * v + 2] = b.z; msg[4 * v + 3] = b.w;
        }
#pragma unroll
        for (int k = 0; k < 4; k++) {
            float ek = ev[k];
#pragma unroll
            for (int v = 0; v < 4; v++)
                addv4(&msg[4 * v], ek, ld4s(lw + k * 16 + 4 * v));
        }

        int sl = (lane & ~3) | src;
#pragma unroll
        for (int d = 0; d < 16; d++) {
            float hs = __shfl_sync(0xffffffffu, h[d], sl);
            agg[d] += fmaxf(msg[d] + hs, 0.f);
        }
    }

    float in[16];
#pragma unroll
    for (int d = 0; d < 16; d++) in[d] = h[d] + agg[d];

    float out[16];
#pragma unroll
    for (int v = 0; v < 4; v++) {
        float4 b = ld4s(b2 + 4 * v);
        out[4 * v + 0] = b.x; out[4 * v + 1] = b.y;
        out[4 * v + 2] = b.z; out[4 * v + 3] = b.w;
    }

#pragma unroll
    for (int c = 0; c < 4; c++) {
        float hid[16];
#pragma unroll
        for (int v = 0; v < 4; v++) {
            float4 b = ld4s(b1 + c * 16 + 4 * v);
            hid[4 * v + 0] = b.x; hid[4 * v + 1] = b.y;
            hid[4 * v + 2] = b.z; hid[4 * v + 3] = b.w;
        }
#pragma unroll
        for (int k = 0; k < 16; k++) {
            float xk = in[k];
#pragma unroll
            for (int v = 0; v < 4; v++)
                addv4(&hid[4 * v], xk, ld4s(w1 + k * 64 + c * 16 + 4 * v));
        }
#pragma unroll
        for (int u = 0; u < 16; u++) hid[u] = fmaxf(hid[u], 0.f);
#pragma unroll
        for (int u = 0; u < 16; u++) {
            float hu = hid[u];
            const float* r = w2 + (c * 16 + u) * 16;
#pragma unroll
            for (int v = 0; v < 4; v++)
                addv4(&out[4 * v], hu, ld4s(r + 4 * v));
        }
    }

    // LayerNorm (ddof=0) + relu
    float mean = 0.f;
#pragma unroll
    for (int d = 0; d < 16; d++) mean += out[d];
    mean *= (1.f / 16.f);
    float var = 0.f;
#pragma unroll
    for (int d = 0; d < 16; d++) { float dd = out[d] - mean; var = fmaf(dd, dd, var); }
    var *= (1.f / 16.f);
    float inv = rsqrtf(var + 1e-5f);
#pragma unroll
    for (int d = 0; d < 16; d++) h[d] = fmaxf((out[d] - mean) * inv, 0.f);
}

__global__ void __launch_bounds__(NTHREADS)
gnn_kernel(Params p)
{
    __shared__ float S[SMEM_FLOATS];

    // stage all weights into shared
    {
        const int sizes[24] = {80,16,256,16, 80,16,256,16,
                               64,16,1024,64,1024,16,
                               64,16,1024,64,1024,16,
                               2048,64,64,1};
        const int offs[24]  = {JE_W1,JE_B1,JE_W2,JE_B2, MU_W1,MU_B1,MU_W2,MU_B2,
                               L1_W,L1_B,M1_W1,M1_B1,M1_W2,M1_B2,
                               L2_W,L2_B,M2_W1,M2_B1,M2_W2,M2_B2,
                               FC_W1,FC_B1,FC_W2,0};
        for (int a = 0; a < 23; a++) {
            const float* src = p.w[a];
            float* dst = S + offs[a];
            int n = sizes[a];
            for (int i = threadIdx.x; i < n; i += NTHREADS) dst[i] = src[i];
        }
    }
    __syncthreads();

    const float fcb2 = __ldg(p.w[23]);

    int tid = threadIdx.x;
    int lane = tid & 31;
    int node = lane & 3;
    long long total = (long long)p.G * 4;
    long long stride = (long long)gridDim.x * NTHREADS;

    for (long long slot = (long long)blockIdx.x * NTHREADS + tid;
         slot - lane < total; slot += stride)
    {
        long long gl = slot >> 2;
        int graph = (gl < p.G) ? (int)gl : (p.G - 1);

        // ---- heterogeneous encoder ----
        float xin[5];
        {
            const float* xr = p.x + (long long)(graph * 4 + node) * 5;
#pragma unroll
            for (int k = 0; k < 5; k++) xin[k] = __ldg(xr + k);
        }
        const float* w1 = (node == 3) ? (S + MU_W1) : (S + JE_W1);
        const float* b1 = (node == 3) ? (S + MU_B1) : (S + JE_B1);
        const float* w2 = (node == 3) ? (S + MU_W2) : (S + JE_W2);
        const float* b2 = (node == 3) ? (S + MU_B2) : (S + JE_B2);

        float t[16];
#pragma unroll
        for (int v = 0; v < 4; v++) {
            float4 b = ld4s(b1 + 4 * v);
            t[4 * v + 0] = b.x; t[4 * v + 1] = b.y;
            t[4 * v + 2] = b.z; t[4 * v + 3] = b.w;
        }
#pragma unroll
        for (int k = 0; k < 5; k++) {
            float xk = xin[k];
#pragma unroll
            for (int v = 0; v < 4; v++)
                addv4(&t[4 * v], xk, ld4s(w1 + k * 16 + 4 * v));
        }
#pragma unroll
        for (int u = 0; u < 16; u++) t[u] = fmaxf(t[u], 0.f);

        float h[16];
#pragma unroll
        for (int v = 0; v < 4; v++) {
            float4 b = ld4s(b2 + 4 * v);
            h[4 * v + 0] = b.x; h[4 * v + 1] = b.y;
            h[4 * v + 2] = b.z; h[4 * v + 3] = b.w;
        }
#pragma unroll
        for (int k = 0; k < 16; k++) {
            float tk = t[k];
#pragma unroll
            for (int v = 0; v < 4; v++)
                addv4(&h[4 * v], tk, ld4s(w2 + k * 16 + 4 * v));
        }

        // ---- two GINE blocks ----
        gine_ln_relu(h, lane, node, graph, p.ea,
                     S + L1_W, S + L1_B, S + M1_W1, S + M1_B1, S + M1_W2, S + M1_B2);
        gine_ln_relu(h, lane, node, graph, p.ea,
                     S + L2_W, S + L2_B, S + M2_W1, S + M2_B1, S + M2_W2, S + M2_B2);

        // ---- pooling (mean + max over the 4 lanes of the graph) ----
        float g[32];
#pragma unroll
        for (int d = 0; d < 16; d++) {
            float s = h[d];
            s += __shfl_xor_sync(0xffffffffu, s, 1);
            s += __shfl_xor_sync(0xffffffffu, s, 2);
            float mx = h[d];
            mx = fmaxf(mx, __shfl_xor_sync(0xffffffffu, mx, 1));
            mx = fmaxf(mx, __shfl_xor_sync(0xffffffffu, mx, 2));
            g[d] = s * 0.25f;
            g[16 + d] = mx;
        }
        // LN over 32
        {
            float mean = 0.f;
#pragma unroll
            for (int d = 0; d < 32; d++) mean += g[d];
            mean *= (1.f / 32.f);
            float var = 0.f;
#pragma unroll
            for (int d = 0; d < 32; d++) { float dd = g[d] - mean; var = fmaf(dd, dd, var); }
            var *= (1.f / 32.f);
            float inv = rsqrtf(var + 1e-5f);
#pragma unroll
            for (int d = 0; d < 32; d++) g[d] = (g[d] - mean) * inv;
        }

        // ---- FC head: 32 -> 64 -> 1, hidden split across the 4 lanes ----
        float acc = 0.f;
#pragma unroll
        for (int uv = 0; uv < 4; uv++) {
            float4 a = ld4s(S + FC_B1 + node * 16 + uv * 4);
            float av[4] = {a.x, a.y, a.z, a.w};
#pragma unroll
            for (int k = 0; k < 32; k++)
                addv4(av, g[k], ld4s(S + FC_W1 + k * 64 + node * 16 + uv * 4));
            float4 wv = ld4s(S + FC_W2 + node * 16 + uv * 4);
            acc = fmaf(fmaxf(av[0], 0.f), wv.x, acc);
            acc = fmaf(fmaxf(av[1], 0.f), wv.y, acc);
            acc = fmaf(fmaxf(av[2], 0.f), wv.z, acc);
            acc = fmaf(fmaxf(av[3], 0.f), wv.w, acc);
        }
        acc += __shfl_xor_sync(0xffffffffu, acc, 1);
        acc += __shfl_xor_sync(0xffffffffu, acc, 2);

        if (node == 0 && slot < total)
            p.out[graph] = acc + fcb2;
    }
}

extern "C" void kernel_launch(void* const* d_in, const int* in_sizes, int n_in,
                              void* d_out, int out_size)
{
    Params p;
    p.x  = (const float*)d_in[0];
    p.ea = (const float*)d_in[1];
    for (int i = 0; i < 24; i++) p.w[i] = (const float*)d_in[2 + i];
    p.out = (float*)d_out;
    p.G = in_sizes[0] / 20;            // x is [G*4, 5]

    long long total = (long long)p.G * 4;
    int blocks = (int)((total + NTHREADS - 1) / NTHREADS);
    if (blocks > 888) blocks = 888;    // persistent grid: ~6 blocks/SM target
    if (blocks < 1) blocks = 1;
    gnn_kernel<<<blocks, NTHREADS>>>(p);
}